// round 1
// baseline (speedup 1.0000x reference)
#include <cuda_runtime.h>
#include <math.h>

#define EPSV  1e-5f
#define SLOPE 0.01f

#define B_    16
#define C_    512
#define NHW   4096
#define D_    128
#define K_    16
#define TN    128
#define TILES 32   // NHW / TN

// ---------------- scratch (device globals: no runtime allocation) ----------------
__device__ float g_sp[C_], g_tp[C_], g_g1[C_], g_h1[C_];
__device__ float g_s2[D_], g_t2[D_];
__device__ float g_c2k[K_];
__device__ float g_wT[C_ * D_];                  // conv_w transposed (C, D)
__device__ float g_spa[B_ * NHW];                // spatial SE (post-sigmoid)
__device__ float g_chn[B_ * C_];                 // channel SE (post-sigmoid)
__device__ float g_partE[B_ * TILES * K_ * D_];  // per-tile partial E
__device__ float g_partAsum[B_ * TILES * K_];    // per-tile partial sum_n A

// ---------------- fold ABN constants ----------------
__global__ void k_prep(const float* __restrict__ pg, const float* __restrict__ pb,
                       const float* __restrict__ pm, const float* __restrict__ pv,
                       const float* __restrict__ a1g, const float* __restrict__ a1b,
                       const float* __restrict__ a1m, const float* __restrict__ a1v,
                       const float* __restrict__ cb, const float* __restrict__ a2g,
                       const float* __restrict__ a2b, const float* __restrict__ a2m,
                       const float* __restrict__ a2v, const float* __restrict__ cw) {
  const int t = threadIdx.x;
  for (int c = t; c < C_; c += 256) {
    float s = pg[c] * rsqrtf(pv[c] + EPSV);
    g_sp[c] = s;
    g_tp[c] = pb[c] - pm[c] * s;
    float s1 = a1g[c] * rsqrtf(a1v[c] + EPSV);
    g_g1[c] = s1;
    g_h1[c] = a1b[c] - a1m[c] * s1;
  }
  for (int d = t; d < D_; d += 256) {
    float s2 = a2g[d] * rsqrtf(a2v[d] + EPSV);
    g_s2[d] = s2;
    g_t2[d] = cb[d] * s2 + a2b[d] - a2m[d] * s2;  // conv bias folded in
  }
  for (int k = t; k < K_; k += 256) {
    float a = 0.f;
    for (int d = 0; d < D_; d++) { float v = cw[k * D_ + d]; a += v * v; }
    g_c2k[k] = a;
  }
}

// ---------------- transpose conv_w (D,C) -> (C,D) ----------------
__global__ void k_trans(const float* __restrict__ w) {
  const int i = blockIdx.x * 256 + threadIdx.x;
  if (i < D_ * C_) {
    const int d = i / C_, c = i % C_;
    g_wT[c * D_ + d] = w[i];
  }
}

// ---------------- fused main kernel ----------------
// Per block: batch b, 128 spatial positions. Phase 1: stream x, compute
// pre_x (for spatial SE) and y, SGEMM z = y @ wT with 8x8 register tiles.
// Phase 2 (all in smem): abn2 -> X, scaled-L2 softmax A, partial E / sum A.
//
// Dynamic smem layout (floats):
//   phase1: ys[16*128] @0, ws[16*128] @2048, spa_red[16*128] @4096   (24 KB)
//   phase2: X[128*132] @0, A[128*16] @16896, cw[16*128] @18944,
//           r2[17*128] @20992, scale[16] @23168, c2[16] @23184       (92.8 KB)
#define SMEM_FLOATS 23200

__global__ __launch_bounds__(256, 2)
void k_main(const float* __restrict__ x, const float* __restrict__ spa_w,
            const float* __restrict__ codewords, const float* __restrict__ scalek) {
  extern __shared__ float sm[];
  const int t = threadIdx.x;
  const int b = blockIdx.x >> 5;
  const int tile = blockIdx.x & 31;
  const int n0 = tile * TN;
  const int tn = t >> 4;        // 0..15 : row group (n) / also channel row in loads
  const int td = t & 15;        // 0..15 : col group (d)
  const int nb = td * 8;

  float acc[8][8];
#pragma unroll
  for (int i = 0; i < 8; i++)
#pragma unroll
    for (int j = 0; j < 8; j++) acc[i][j] = 0.f;
  float spa[8] = {0.f, 0.f, 0.f, 0.f, 0.f, 0.f, 0.f, 0.f};

  float* s_ys  = sm;
  float* s_ws  = sm + 2048;
  float* s_spr = sm + 4096;

  const float* xb = x + ((size_t)b * C_) * NHW + n0;

  // ---------------- phase 1: C-loop GEMM + spatial-SE accumulation ----------------
  for (int c0 = 0; c0 < C_; c0 += 16) {
    const int c = c0 + tn;
    const float sp = g_sp[c], tp = g_tp[c], g1 = g_g1[c], h1 = g_h1[c], sw = spa_w[c];
    const float* xr = xb + (size_t)c * NHW + nb;
    float4 va = *reinterpret_cast<const float4*>(xr);
    float4 vb = *reinterpret_cast<const float4*>(xr + 4);
    float u[8] = {va.x, va.y, va.z, va.w, vb.x, vb.y, vb.z, vb.w};
#pragma unroll
    for (int i = 0; i < 8; i++) {
      float xn = fmaf(u[i], sp, tp);
      xn = (xn >= 0.f) ? xn : SLOPE * xn;          // pre_x
      spa[i] = fmaf(xn, sw, spa[i]);               // spatial SE logit partial
      float y = fmaf(xn, g1, h1);
      u[i] = (y >= 0.f) ? y : SLOPE * y;           // y
    }
    *reinterpret_cast<float4*>(&s_ys[tn * 128 + nb])     = make_float4(u[0], u[1], u[2], u[3]);
    *reinterpret_cast<float4*>(&s_ys[tn * 128 + nb + 4]) = make_float4(u[4], u[5], u[6], u[7]);
    *reinterpret_cast<float4*>(&s_ws[tn * 128 + nb]) =
        *reinterpret_cast<const float4*>(&g_wT[c * D_ + nb]);
    *reinterpret_cast<float4*>(&s_ws[tn * 128 + nb + 4]) =
        *reinterpret_cast<const float4*>(&g_wT[c * D_ + nb + 4]);
    __syncthreads();
#pragma unroll
    for (int kc = 0; kc < 16; kc++) {
      float4 y0 = *reinterpret_cast<const float4*>(&s_ys[kc * 128 + tn * 8]);
      float4 y1 = *reinterpret_cast<const float4*>(&s_ys[kc * 128 + tn * 8 + 4]);
      float4 w0 = *reinterpret_cast<const float4*>(&s_ws[kc * 128 + td * 8]);
      float4 w1 = *reinterpret_cast<const float4*>(&s_ws[kc * 128 + td * 8 + 4]);
      float yv[8] = {y0.x, y0.y, y0.z, y0.w, y1.x, y1.y, y1.z, y1.w};
      float wv[8] = {w0.x, w0.y, w0.z, w0.w, w1.x, w1.y, w1.z, w1.w};
#pragma unroll
      for (int i = 0; i < 8; i++)
#pragma unroll
        for (int j = 0; j < 8; j++) acc[i][j] = fmaf(yv[i], wv[j], acc[i][j]);
    }
    __syncthreads();
  }

  // ---------------- spatial SE reduce + sigmoid ----------------
#pragma unroll
  for (int i = 0; i < 8; i++) s_spr[tn * 128 + nb + i] = spa[i];
  __syncthreads();
  if (t < TN) {
    float s = 0.f;
#pragma unroll
    for (int r = 0; r < 16; r++) s += s_spr[r * 128 + t];
    g_spa[b * NHW + n0 + t] = 1.f / (1.f + __expf(-s));
  }
  __syncthreads();

  // ---------------- phase 2 smem layout ----------------
  float* s_X  = sm;            // 128 x 132 (padded)
  float* s_A  = sm + 16896;    // 128 x 16
  float* s_cw = sm + 18944;    // 16 x 128
  float* s_r2 = sm + 20992;    // (1 + 16) x 128
  float* s_sc = sm + 23168;    // 16
  float* s_c2 = sm + 23184;    // 16

  // abn2 + leaky_relu -> X tile into smem
  {
    float s2v[8], t2v[8];
#pragma unroll
    for (int j = 0; j < 8; j++) { s2v[j] = g_s2[td * 8 + j]; t2v[j] = g_t2[td * 8 + j]; }
#pragma unroll
    for (int i = 0; i < 8; i++) {
      float v[8];
#pragma unroll
      for (int j = 0; j < 8; j++) {
        float z = fmaf(acc[i][j], s2v[j], t2v[j]);
        v[j] = (z >= 0.f) ? z : SLOPE * z;
      }
      const int row = tn * 8 + i;
      *reinterpret_cast<float4*>(&s_X[row * 132 + td * 8])     = make_float4(v[0], v[1], v[2], v[3]);
      *reinterpret_cast<float4*>(&s_X[row * 132 + td * 8 + 4]) = make_float4(v[4], v[5], v[6], v[7]);
    }
  }
#pragma unroll
  for (int i = 0; i < 8; i++) s_cw[t * 8 + i] = codewords[t * 8 + i];
  if (t < K_) { s_sc[t] = scalek[t]; s_c2[t] = g_c2k[t]; }
  __syncthreads();

  // ---------------- scaled-L2 softmax assignment A ----------------
  {
    const int n = t & 127;
    const int half = t >> 7;                 // each n handled by 2 threads (64 dims each)
    const float* xr = &s_X[n * 132 + half * 64];
    float px2 = 0.f;
    float pxc[16];
#pragma unroll
    for (int k = 0; k < 16; k++) pxc[k] = 0.f;
#pragma unroll 4
    for (int ch = 0; ch < 16; ch++) {
      float4 xv = *reinterpret_cast<const float4*>(xr + ch * 4);
      px2 = fmaf(xv.x, xv.x, px2); px2 = fmaf(xv.y, xv.y, px2);
      px2 = fmaf(xv.z, xv.z, px2); px2 = fmaf(xv.w, xv.w, px2);
      const int dd = half * 64 + ch * 4;
#pragma unroll
      for (int k = 0; k < 16; k++) {
        float4 cv = *reinterpret_cast<const float4*>(&s_cw[k * 128 + dd]);
        pxc[k] = fmaf(xv.x, cv.x, pxc[k]);
        pxc[k] = fmaf(xv.y, cv.y, pxc[k]);
        pxc[k] = fmaf(xv.z, cv.z, pxc[k]);
        pxc[k] = fmaf(xv.w, cv.w, pxc[k]);
      }
    }
    if (half) {
      s_r2[n] = px2;
#pragma unroll
      for (int k = 0; k < 16; k++) s_r2[128 + k * 128 + n] = pxc[k];
    }
    __syncthreads();
    if (!half) {
      const float x2 = px2 + s_r2[n];
      float sl[16];
      float m = -1e30f;
#pragma unroll
      for (int k = 0; k < 16; k++) {
        float xc = pxc[k] + s_r2[128 + k * 128 + n];
        float v = s_sc[k] * (x2 - 2.f * xc + s_c2[k]);
        sl[k] = v;
        m = fmaxf(m, v);
      }
      float ssum = 0.f;
#pragma unroll
      for (int k = 0; k < 16; k++) { float e2 = __expf(sl[k] - m); sl[k] = e2; ssum += e2; }
      const float inv = 1.f / ssum;
#pragma unroll
      for (int k = 0; k < 16; k++) s_A[n * 16 + k] = sl[k] * inv;
    }
    __syncthreads();
  }

  // ---------------- partial E = A^T @ X and sum_n A ----------------
  {
    const int k = t >> 4;
    const int d0 = (t & 15) * 8;
    float e[8];
#pragma unroll
    for (int j = 0; j < 8; j++) e[j] = 0.f;
    float asum = 0.f;
    for (int n = 0; n < 128; n++) {
      const float a = s_A[n * 16 + k];
      asum += a;
      float4 x0 = *reinterpret_cast<const float4*>(&s_X[n * 132 + d0]);
      float4 x1 = *reinterpret_cast<const float4*>(&s_X[n * 132 + d0 + 4]);
      e[0] = fmaf(a, x0.x, e[0]); e[1] = fmaf(a, x0.y, e[1]);
      e[2] = fmaf(a, x0.z, e[2]); e[3] = fmaf(a, x0.w, e[3]);
      e[4] = fmaf(a, x1.x, e[4]); e[5] = fmaf(a, x1.y, e[5]);
      e[6] = fmaf(a, x1.z, e[6]); e[7] = fmaf(a, x1.w, e[7]);
    }
    const int base = ((b * TILES + tile) * K_ + k) * D_ + d0;
    *reinterpret_cast<float4*>(&g_partE[base])     = make_float4(e[0], e[1], e[2], e[3]);
    *reinterpret_cast<float4*>(&g_partE[base + 4]) = make_float4(e[4], e[5], e[6], e[7]);
    if ((t & 15) == 0) g_partAsum[(b * TILES + tile) * K_ + k] = asum;
  }
}

// ---------------- reduce partials -> enc (to d_out) + channel SE ----------------
__global__ void k_reduce(const float* __restrict__ codewords,
                         const float* __restrict__ se_w,
                         const float* __restrict__ se_b,
                         float* __restrict__ out_enc) {
  __shared__ float s_enc[2048];
  __shared__ float s_red[256];
  __shared__ float s_as[16];
  const int b = blockIdx.x;
  const int t = threadIdx.x;
  if (t < 16) {
    float a = 0.f;
    for (int tile = 0; tile < TILES; tile++) a += g_partAsum[(b * TILES + tile) * K_ + t];
    s_as[t] = a;
  }
  __syncthreads();
  float e[8];
#pragma unroll
  for (int j = 0; j < 8; j++) e[j] = 0.f;
  const int base = b * TILES * 2048 + t * 8;
  for (int tile = 0; tile < TILES; tile++) {
    float4 p0 = *reinterpret_cast<const float4*>(&g_partE[base + tile * 2048]);
    float4 p1 = *reinterpret_cast<const float4*>(&g_partE[base + tile * 2048 + 4]);
    e[0] += p0.x; e[1] += p0.y; e[2] += p0.z; e[3] += p0.w;
    e[4] += p1.x; e[5] += p1.y; e[6] += p1.z; e[7] += p1.w;
  }
  const int k = t >> 4;
  const int d0 = (t & 15) * 8;
  const float as = s_as[k];
#pragma unroll
  for (int j = 0; j < 8; j++) e[j] -= as * codewords[k * D_ + d0 + j];
  float sq = 0.f;
#pragma unroll
  for (int j = 0; j < 8; j++) sq = fmaf(e[j], e[j], sq);
  s_red[t] = sq;
  __syncthreads();
  for (int s = 128; s > 0; s >>= 1) {
    if (t < s) s_red[t] += s_red[t + s];
    __syncthreads();
  }
  const float rn = 1.f / fmaxf(sqrtf(s_red[0]), 1e-12f);
#pragma unroll
  for (int j = 0; j < 8; j++) {
    const float v = e[j] * rn;
    out_enc[b * 2048 + t * 8 + j] = v;
    s_enc[t * 8 + j] = v;
  }
  __syncthreads();
  // channel SE: one warp computes 64 channels cooperatively
  const int w = t >> 5, lane = t & 31;
  for (int cc = 0; cc < 64; cc++) {
    const int c = w * 64 + cc;
    const float* wr = se_w + (size_t)c * 2048;
    float p = 0.f;
#pragma unroll 8
    for (int i = 0; i < 64; i++) {
      const int idx = lane + (i << 5);
      p = fmaf(s_enc[idx], wr[idx], p);
    }
#pragma unroll
    for (int o = 16; o > 0; o >>= 1) p += __shfl_xor_sync(0xffffffffu, p, o);
    if (lane == 0) g_chn[b * C_ + c] = 1.f / (1.f + __expf(-(p + se_b[c])));
  }
}

// ---------------- final gating: out = x * spa_se * chn_se ----------------
__global__ void k_out(const float* __restrict__ x, float* __restrict__ out) {
  const int i = blockIdx.x * 256 + threadIdx.x;   // float4 index
  float4 v = reinterpret_cast<const float4*>(x)[i];
  const int b = i >> 19;           // C_*NHW/4 = 524288
  const int rem = i & 524287;
  const int c = rem >> 10;         // NHW/4 = 1024
  const int n4 = rem & 1023;
  const float4 sp = reinterpret_cast<const float4*>(g_spa)[b * 1024 + n4];
  const float ch = g_chn[b * C_ + c];
  float4 o;
  o.x = v.x * sp.x * ch;
  o.y = v.y * sp.y * ch;
  o.z = v.z * sp.z * ch;
  o.w = v.w * sp.w * ch;
  reinterpret_cast<float4*>(out)[i] = o;
}

extern "C" void kernel_launch(void* const* d_in, const int* in_sizes, int n_in,
                              void* d_out, int out_size) {
  const float* x    = (const float*)d_in[0];
  const float* pg   = (const float*)d_in[1];
  const float* pb   = (const float*)d_in[2];
  const float* pm   = (const float*)d_in[3];
  const float* pv   = (const float*)d_in[4];
  const float* a1g  = (const float*)d_in[5];
  const float* a1b  = (const float*)d_in[6];
  const float* a1m  = (const float*)d_in[7];
  const float* a1v  = (const float*)d_in[8];
  const float* cwv  = (const float*)d_in[9];   // conv_w (D, C)
  const float* cb   = (const float*)d_in[10];
  const float* a2g  = (const float*)d_in[11];
  const float* a2b  = (const float*)d_in[12];
  const float* a2m  = (const float*)d_in[13];
  const float* a2v  = (const float*)d_in[14];
  const float* cdw  = (const float*)d_in[15];  // codewords (K, D)
  const float* sck  = (const float*)d_in[16];  // scale (K,)
  const float* sew  = (const float*)d_in[17];  // se_w (C, K*D)
  const float* seb  = (const float*)d_in[18];
  const float* spw  = (const float*)d_in[19];  // spa_w (C,)
  float* out = (float*)d_out;

  cudaFuncSetAttribute(k_main, cudaFuncAttributeMaxDynamicSharedMemorySize,
                       SMEM_FLOATS * (int)sizeof(float));

  k_prep<<<1, 256>>>(pg, pb, pm, pv, a1g, a1b, a1m, a1v, cb, a2g, a2b, a2m, a2v, cdw);
  k_trans<<<(D_ * C_ + 255) / 256, 256>>>(cwv);
  k_main<<<B_ * TILES, 256, SMEM_FLOATS * sizeof(float)>>>(x, spw, cdw, sck);
  k_reduce<<<B_, 256>>>(cdw, sew, seb, out);
  k_out<<<(B_ * C_ * NHW / 4) / 256, 256>>>(x, out + B_ * K_ * D_);
}

// round 2
// speedup vs baseline: 1.6060x; 1.6060x over previous
#include <cuda_runtime.h>
#include <math.h>

#define EPSV  1e-5f
#define SLOPE 0.01f

#define B_    16
#define C_    512
#define NHW   4096
#define D_    128
#define K_    16
#define TN    128
#define TILES 32   // NHW / TN

// ---------------- scratch (device globals: no runtime allocation) ----------------
__device__ float g_sp[C_], g_tp[C_], g_g1[C_], g_h1[C_];
__device__ float g_s2[D_], g_t2[D_];
__device__ float g_c2k[K_];
__device__ float g_wT[C_ * D_];                  // conv_w transposed (C, D)
__device__ float g_spa[B_ * NHW];                // spatial SE (post-sigmoid)
__device__ float g_chn[B_ * C_];                 // channel SE (post-sigmoid)
__device__ float g_partE[B_ * TILES * K_ * D_];  // per-tile partial E
__device__ float g_partAsum[B_ * TILES * K_];    // per-tile partial sum_n A

// ---------------- fold ABN constants ----------------
__global__ void k_prep(const float* __restrict__ pg, const float* __restrict__ pb,
                       const float* __restrict__ pm, const float* __restrict__ pv,
                       const float* __restrict__ a1g, const float* __restrict__ a1b,
                       const float* __restrict__ a1m, const float* __restrict__ a1v,
                       const float* __restrict__ cb, const float* __restrict__ a2g,
                       const float* __restrict__ a2b, const float* __restrict__ a2m,
                       const float* __restrict__ a2v, const float* __restrict__ cw) {
  const int t = threadIdx.x;
  for (int c = t; c < C_; c += 256) {
    float s = pg[c] * rsqrtf(pv[c] + EPSV);
    g_sp[c] = s;
    g_tp[c] = pb[c] - pm[c] * s;
    float s1 = a1g[c] * rsqrtf(a1v[c] + EPSV);
    g_g1[c] = s1;
    g_h1[c] = a1b[c] - a1m[c] * s1;
  }
  for (int d = t; d < D_; d += 256) {
    float s2 = a2g[d] * rsqrtf(a2v[d] + EPSV);
    g_s2[d] = s2;
    g_t2[d] = cb[d] * s2 + a2b[d] - a2m[d] * s2;  // conv bias folded in
  }
  for (int k = t; k < K_; k += 256) {
    float a = 0.f;
    for (int d = 0; d < D_; d++) { float v = cw[k * D_ + d]; a += v * v; }
    g_c2k[k] = a;
  }
}

// ---------------- transpose conv_w (D,C) -> (C,D) ----------------
__global__ void k_trans(const float* __restrict__ w) {
  const int i = blockIdx.x * 256 + threadIdx.x;
  if (i < D_ * C_) {
    const int d = i / C_, c = i % C_;
    g_wT[c * D_ + d] = w[i];
  }
}

// ---------------- fused main kernel ----------------
#define SMEM_FLOATS 23200

__global__ __launch_bounds__(256, 2)
void k_main(const float* __restrict__ x, const float* __restrict__ spa_w,
            const float* __restrict__ codewords, const float* __restrict__ scalek) {
  extern __shared__ float sm[];
  const int t = threadIdx.x;
  const int b = blockIdx.x >> 5;
  const int tile = blockIdx.x & 31;
  const int n0 = tile * TN;
  const int tn = t >> 4;        // 0..15 : row group (n) / also channel row in loads
  const int td = t & 15;        // 0..15 : col group (d)
  const int nb = td * 8;

  float acc[8][8];
#pragma unroll
  for (int i = 0; i < 8; i++)
#pragma unroll
    for (int j = 0; j < 8; j++) acc[i][j] = 0.f;
  float spa[8] = {0.f, 0.f, 0.f, 0.f, 0.f, 0.f, 0.f, 0.f};

  float* s_ys  = sm;
  float* s_ws  = sm + 2048;
  float* s_spr = sm + 4096;

  const float* xb = x + ((size_t)b * C_) * NHW + n0;

  // ---------------- phase 1: C-loop GEMM + spatial-SE accumulation ----------------
  for (int c0 = 0; c0 < C_; c0 += 16) {
    const int c = c0 + tn;
    const float sp = g_sp[c], tp = g_tp[c], g1 = g_g1[c], h1 = g_h1[c], sw = spa_w[c];
    const float* xr = xb + (size_t)c * NHW + nb;
    float4 va = *reinterpret_cast<const float4*>(xr);
    float4 vb = *reinterpret_cast<const float4*>(xr + 4);
    float u[8] = {va.x, va.y, va.z, va.w, vb.x, vb.y, vb.z, vb.w};
#pragma unroll
    for (int i = 0; i < 8; i++) {
      float xn = fmaf(u[i], sp, tp);
      xn = (xn >= 0.f) ? xn : SLOPE * xn;          // pre_x
      spa[i] = fmaf(xn, sw, spa[i]);               // spatial SE logit partial
      float y = fmaf(xn, g1, h1);
      u[i] = (y >= 0.f) ? y : SLOPE * y;           // y
    }
    *reinterpret_cast<float4*>(&s_ys[tn * 128 + nb])     = make_float4(u[0], u[1], u[2], u[3]);
    *reinterpret_cast<float4*>(&s_ys[tn * 128 + nb + 4]) = make_float4(u[4], u[5], u[6], u[7]);
    *reinterpret_cast<float4*>(&s_ws[tn * 128 + nb]) =
        *reinterpret_cast<const float4*>(&g_wT[c * D_ + nb]);
    *reinterpret_cast<float4*>(&s_ws[tn * 128 + nb + 4]) =
        *reinterpret_cast<const float4*>(&g_wT[c * D_ + nb + 4]);
    __syncthreads();
#pragma unroll
    for (int kc = 0; kc < 16; kc++) {
      float4 y0 = *reinterpret_cast<const float4*>(&s_ys[kc * 128 + tn * 8]);
      float4 y1 = *reinterpret_cast<const float4*>(&s_ys[kc * 128 + tn * 8 + 4]);
      float4 w0 = *reinterpret_cast<const float4*>(&s_ws[kc * 128 + td * 8]);
      float4 w1 = *reinterpret_cast<const float4*>(&s_ws[kc * 128 + td * 8 + 4]);
      float yv[8] = {y0.x, y0.y, y0.z, y0.w, y1.x, y1.y, y1.z, y1.w};
      float wv[8] = {w0.x, w0.y, w0.z, w0.w, w1.x, w1.y, w1.z, w1.w};
#pragma unroll
      for (int i = 0; i < 8; i++)
#pragma unroll
        for (int j = 0; j < 8; j++) acc[i][j] = fmaf(yv[i], wv[j], acc[i][j]);
    }
    __syncthreads();
  }

  // ---------------- spatial SE reduce + sigmoid ----------------
#pragma unroll
  for (int i = 0; i < 8; i++) s_spr[tn * 128 + nb + i] = spa[i];
  __syncthreads();
  if (t < TN) {
    float s = 0.f;
#pragma unroll
    for (int r = 0; r < 16; r++) s += s_spr[r * 128 + t];
    g_spa[b * NHW + n0 + t] = 1.f / (1.f + __expf(-s));
  }
  __syncthreads();

  // ---------------- phase 2 smem layout ----------------
  float* s_X  = sm;            // 128 x 132 (padded)
  float* s_A  = sm + 16896;    // 128 x 16
  float* s_cw = sm + 18944;    // 16 x 128
  float* s_r2 = sm + 20992;    // (1 + 16) x 128
  float* s_sc = sm + 23168;    // 16
  float* s_c2 = sm + 23184;    // 16

  // abn2 + leaky_relu -> X tile into smem
  {
    float s2v[8], t2v[8];
#pragma unroll
    for (int j = 0; j < 8; j++) { s2v[j] = g_s2[td * 8 + j]; t2v[j] = g_t2[td * 8 + j]; }
#pragma unroll
    for (int i = 0; i < 8; i++) {
      float v[8];
#pragma unroll
      for (int j = 0; j < 8; j++) {
        float z = fmaf(acc[i][j], s2v[j], t2v[j]);
        v[j] = (z >= 0.f) ? z : SLOPE * z;
      }
      const int row = tn * 8 + i;
      *reinterpret_cast<float4*>(&s_X[row * 132 + td * 8])     = make_float4(v[0], v[1], v[2], v[3]);
      *reinterpret_cast<float4*>(&s_X[row * 132 + td * 8 + 4]) = make_float4(v[4], v[5], v[6], v[7]);
    }
  }
#pragma unroll
  for (int i = 0; i < 8; i++) s_cw[t * 8 + i] = codewords[t * 8 + i];
  if (t < K_) { s_sc[t] = scalek[t]; s_c2[t] = g_c2k[t]; }
  __syncthreads();

  // ---------------- scaled-L2 softmax assignment A ----------------
  {
    const int n = t & 127;
    const int half = t >> 7;                 // each n handled by 2 threads (64 dims each)
    const float* xr = &s_X[n * 132 + half * 64];
    float px2 = 0.f;
    float pxc[16];
#pragma unroll
    for (int k = 0; k < 16; k++) pxc[k] = 0.f;
#pragma unroll 4
    for (int ch = 0; ch < 16; ch++) {
      float4 xv = *reinterpret_cast<const float4*>(xr + ch * 4);
      px2 = fmaf(xv.x, xv.x, px2); px2 = fmaf(xv.y, xv.y, px2);
      px2 = fmaf(xv.z, xv.z, px2); px2 = fmaf(xv.w, xv.w, px2);
      const int dd = half * 64 + ch * 4;
#pragma unroll
      for (int k = 0; k < 16; k++) {
        float4 cv = *reinterpret_cast<const float4*>(&s_cw[k * 128 + dd]);
        pxc[k] = fmaf(xv.x, cv.x, pxc[k]);
        pxc[k] = fmaf(xv.y, cv.y, pxc[k]);
        pxc[k] = fmaf(xv.z, cv.z, pxc[k]);
        pxc[k] = fmaf(xv.w, cv.w, pxc[k]);
      }
    }
    if (half) {
      s_r2[n] = px2;
#pragma unroll
      for (int k = 0; k < 16; k++) s_r2[128 + k * 128 + n] = pxc[k];
    }
    __syncthreads();
    if (!half) {
      const float x2 = px2 + s_r2[n];
      float sl[16];
      float m = -1e30f;
#pragma unroll
      for (int k = 0; k < 16; k++) {
        float xc = pxc[k] + s_r2[128 + k * 128 + n];
        float v = s_sc[k] * (x2 - 2.f * xc + s_c2[k]);
        sl[k] = v;
        m = fmaxf(m, v);
      }
      float ssum = 0.f;
#pragma unroll
      for (int k = 0; k < 16; k++) { float e2 = __expf(sl[k] - m); sl[k] = e2; ssum += e2; }
      const float inv = 1.f / ssum;
#pragma unroll
      for (int k = 0; k < 16; k++) s_A[n * 16 + k] = sl[k] * inv;
    }
    __syncthreads();
  }

  // ---------------- partial E = A^T @ X and sum_n A ----------------
  {
    const int k = t >> 4;
    const int d0 = (t & 15) * 8;
    float e[8];
#pragma unroll
    for (int j = 0; j < 8; j++) e[j] = 0.f;
    float asum = 0.f;
    for (int n = 0; n < 128; n++) {
      const float a = s_A[n * 16 + k];
      asum += a;
      float4 x0 = *reinterpret_cast<const float4*>(&s_X[n * 132 + d0]);
      float4 x1 = *reinterpret_cast<const float4*>(&s_X[n * 132 + d0 + 4]);
      e[0] = fmaf(a, x0.x, e[0]); e[1] = fmaf(a, x0.y, e[1]);
      e[2] = fmaf(a, x0.z, e[2]); e[3] = fmaf(a, x0.w, e[3]);
      e[4] = fmaf(a, x1.x, e[4]); e[5] = fmaf(a, x1.y, e[5]);
      e[6] = fmaf(a, x1.z, e[6]); e[7] = fmaf(a, x1.w, e[7]);
    }
    const int base = ((b * TILES + tile) * K_ + k) * D_ + d0;
    *reinterpret_cast<float4*>(&g_partE[base])     = make_float4(e[0], e[1], e[2], e[3]);
    *reinterpret_cast<float4*>(&g_partE[base + 4]) = make_float4(e[4], e[5], e[6], e[7]);
    if ((t & 15) == 0) g_partAsum[(b * TILES + tile) * K_ + k] = asum;
  }
}

// ---------------- reduce partials -> enc (normalized), written to d_out ----------------
__global__ void k_reduce(const float* __restrict__ codewords,
                         float* __restrict__ out_enc) {
  __shared__ float s_red[256];
  __shared__ float s_as[16];
  const int b = blockIdx.x;
  const int t = threadIdx.x;
  if (t < 16) {
    float a = 0.f;
    for (int tile = 0; tile < TILES; tile++) a += g_partAsum[(b * TILES + tile) * K_ + t];
    s_as[t] = a;
  }
  __syncthreads();
  float e[8];
#pragma unroll
  for (int j = 0; j < 8; j++) e[j] = 0.f;
  const int base = b * TILES * 2048 + t * 8;
  for (int tile = 0; tile < TILES; tile++) {
    float4 p0 = *reinterpret_cast<const float4*>(&g_partE[base + tile * 2048]);
    float4 p1 = *reinterpret_cast<const float4*>(&g_partE[base + tile * 2048 + 4]);
    e[0] += p0.x; e[1] += p0.y; e[2] += p0.z; e[3] += p0.w;
    e[4] += p1.x; e[5] += p1.y; e[6] += p1.z; e[7] += p1.w;
  }
  const int k = t >> 4;
  const int d0 = (t & 15) * 8;
  const float as = s_as[k];
#pragma unroll
  for (int j = 0; j < 8; j++) e[j] -= as * codewords[k * D_ + d0 + j];
  float sq = 0.f;
#pragma unroll
  for (int j = 0; j < 8; j++) sq = fmaf(e[j], e[j], sq);
  s_red[t] = sq;
  __syncthreads();
  for (int s = 128; s > 0; s >>= 1) {
    if (t < s) s_red[t] += s_red[t + s];
    __syncthreads();
  }
  const float rn = 1.f / fmaxf(sqrtf(s_red[0]), 1e-12f);
  float4 o0 = make_float4(e[0] * rn, e[1] * rn, e[2] * rn, e[3] * rn);
  float4 o1 = make_float4(e[4] * rn, e[5] * rn, e[6] * rn, e[7] * rn);
  *reinterpret_cast<float4*>(&out_enc[b * 2048 + t * 8])     = o0;
  *reinterpret_cast<float4*>(&out_enc[b * 2048 + t * 8 + 4]) = o1;
}

// ---------------- channel SE: one block per output channel, all batches ----------------
// Reads enc (16x2048, hot in L2) and one 8KB se_w row staged in smem.
__global__ __launch_bounds__(256)
void k_chse(const float* __restrict__ se_w, const float* __restrict__ se_b,
            const float* __restrict__ enc) {
  __shared__ float sw[2048];
  const int c = blockIdx.x;
  const int t = threadIdx.x;
  const float* wr = se_w + (size_t)c * 2048;
#pragma unroll
  for (int i = 0; i < 8; i++) sw[t + i * 256] = wr[t + i * 256];
  __syncthreads();
  const int w = t >> 5, lane = t & 31;   // 8 warps, 2 batches each
  const float bias = se_b[c];
#pragma unroll
  for (int bb = 0; bb < 2; bb++) {
    const int b = w * 2 + bb;
    const float* er = enc + b * 2048;
    float p = 0.f;
#pragma unroll 8
    for (int i = 0; i < 64; i++) {
      const int idx = lane + (i << 5);
      p = fmaf(er[idx], sw[idx], p);
    }
#pragma unroll
    for (int o = 16; o > 0; o >>= 1) p += __shfl_xor_sync(0xffffffffu, p, o);
    if (lane == 0) g_chn[b * C_ + c] = 1.f / (1.f + __expf(-(p + bias)));
  }
}

// ---------------- final gating: out = x * spa_se * chn_se ----------------
__global__ void k_out(const float* __restrict__ x, float* __restrict__ out) {
  const int i = blockIdx.x * 256 + threadIdx.x;   // float4 index
  float4 v = reinterpret_cast<const float4*>(x)[i];
  const int b = i >> 19;           // C_*NHW/4 = 524288
  const int rem = i & 524287;
  const int c = rem >> 10;         // NHW/4 = 1024
  const int n4 = rem & 1023;
  const float4 sp = reinterpret_cast<const float4*>(g_spa)[b * 1024 + n4];
  const float ch = g_chn[b * C_ + c];
  float4 o;
  o.x = v.x * sp.x * ch;
  o.y = v.y * sp.y * ch;
  o.z = v.z * sp.z * ch;
  o.w = v.w * sp.w * ch;
  reinterpret_cast<float4*>(out)[i] = o;
}

extern "C" void kernel_launch(void* const* d_in, const int* in_sizes, int n_in,
                              void* d_out, int out_size) {
  const float* x    = (const float*)d_in[0];
  const float* pg   = (const float*)d_in[1];
  const float* pb   = (const float*)d_in[2];
  const float* pm   = (const float*)d_in[3];
  const float* pv   = (const float*)d_in[4];
  const float* a1g  = (const float*)d_in[5];
  const float* a1b  = (const float*)d_in[6];
  const float* a1m  = (const float*)d_in[7];
  const float* a1v  = (const float*)d_in[8];
  const float* cwv  = (const float*)d_in[9];   // conv_w (D, C)
  const float* cb   = (const float*)d_in[10];
  const float* a2g  = (const float*)d_in[11];
  const float* a2b  = (const float*)d_in[12];
  const float* a2m  = (const float*)d_in[13];
  const float* a2v  = (const float*)d_in[14];
  const float* cdw  = (const float*)d_in[15];  // codewords (K, D)
  const float* sck  = (const float*)d_in[16];  // scale (K,)
  const float* sew  = (const float*)d_in[17];  // se_w (C, K*D)
  const float* seb  = (const float*)d_in[18];
  const float* spw  = (const float*)d_in[19];  // spa_w (C,)
  float* out = (float*)d_out;

  cudaFuncSetAttribute(k_main, cudaFuncAttributeMaxDynamicSharedMemorySize,
                       SMEM_FLOATS * (int)sizeof(float));

  k_prep<<<1, 256>>>(pg, pb, pm, pv, a1g, a1b, a1m, a1v, cb, a2g, a2b, a2m, a2v, cdw);
  k_trans<<<(D_ * C_ + 255) / 256, 256>>>(cwv);
  k_main<<<B_ * TILES, 256, SMEM_FLOATS * sizeof(float)>>>(x, spw, cdw, sck);
  k_reduce<<<B_, 256>>>(cdw, out);
  k_chse<<<C_, 256>>>(sew, seb, out);
  k_out<<<(B_ * C_ * NHW / 4) / 256, 256>>>(x, out + B_ * K_ * D_);
}